// round 5
// baseline (speedup 1.0000x reference)
#include <cuda_runtime.h>
#include <math.h>

#define SEQ     2048
#define BATCH   2
#define DIM     1024
#define HEADS   16
#define HD      64
#define HIDDEN  4096
#define TOK     (BATCH * SEQ)   // 4096 tokens

// ---------------- scratch (static device globals; no allocation) ----------------
__device__ float g_h [(size_t)TOK * DIM];
__device__ float g_q [(size_t)TOK * DIM];
__device__ float g_k [(size_t)TOK * DIM];
__device__ float g_v [(size_t)TOK * DIM];
__device__ float g_o [(size_t)TOK * DIM];
__device__ float g_x1[(size_t)TOK * DIM];
__device__ float g_h2[(size_t)TOK * DIM];
__device__ float g_a [(size_t)TOK * HIDDEN];

// ---------------- LayerNorm: one block per row (1024 elems, 256 threads) --------
__global__ __launch_bounds__(256) void ln_kernel(
    const float* __restrict__ x, const float* __restrict__ g,
    const float* __restrict__ b, float* __restrict__ out)
{
    __shared__ float red[8];
    __shared__ float sh_mu, sh_rs;
    const int row = blockIdx.x, tid = threadIdx.x;
    const float* xr = x + (size_t)row * DIM;
    float4 v = *(const float4*)(xr + tid * 4);
    float s = v.x + v.y + v.z + v.w;
    #pragma unroll
    for (int o = 16; o; o >>= 1) s += __shfl_xor_sync(0xffffffffu, s, o);
    if ((tid & 31) == 0) red[tid >> 5] = s;
    __syncthreads();
    if (tid == 0) {
        float t = 0.f;
        #pragma unroll
        for (int i = 0; i < 8; i++) t += red[i];
        sh_mu = t * (1.0f / DIM);
    }
    __syncthreads();
    const float mu = sh_mu;
    float d0 = v.x - mu, d1 = v.y - mu, d2 = v.z - mu, d3 = v.w - mu;
    float s2 = d0*d0 + d1*d1 + d2*d2 + d3*d3;
    #pragma unroll
    for (int o = 16; o; o >>= 1) s2 += __shfl_xor_sync(0xffffffffu, s2, o);
    if ((tid & 31) == 0) red[tid >> 5] = s2;
    __syncthreads();
    if (tid == 0) {
        float t = 0.f;
        #pragma unroll
        for (int i = 0; i < 8; i++) t += red[i];
        sh_rs = rsqrtf(t * (1.0f / DIM) + 1e-5f);
    }
    __syncthreads();
    const float rs = sh_rs;
    float4 gg = *(const float4*)(g + tid * 4);
    float4 bb = *(const float4*)(b + tid * 4);
    float4 o4;
    o4.x = d0 * rs * gg.x + bb.x;
    o4.y = d1 * rs * gg.y + bb.y;
    o4.z = d2 * rs * gg.z + bb.z;
    o4.w = d3 * rs * gg.w + bb.w;
    *(float4*)(out + (size_t)row * DIM + tid * 4) = o4;
}

// ---------------- tiled fp32 GEMM: C[M,N] = A[M,K] @ B[K,N] + bias (+epi) -------
// block 128x128, 256 threads, 8x8 per thread, K-tile 16.
enum { EPI_NONE = 0, EPI_GELU = 1, EPI_RES = 2 };

template<int EPI, bool SCATTER>
__global__ __launch_bounds__(256) void gemm_kernel(
    const float* __restrict__ A, const float* __restrict__ B,
    const float* __restrict__ bias, const float* __restrict__ R,
    float* __restrict__ C, int M, int N, int K)
{
    __shared__ float As[16][132];   // transposed A tile, padded (132 keeps f4 align)
    __shared__ float Bs[16][128];
    const int n0 = blockIdx.x * 128, m0 = blockIdx.y * 128;
    const int tid = threadIdx.x;
    const int tx = tid & 15, ty = tid >> 4;

    float acc[8][8];
    #pragma unroll
    for (int i = 0; i < 8; i++)
        #pragma unroll
        for (int j = 0; j < 8; j++) acc[i][j] = 0.f;

    const int arow = tid >> 2;          // 0..63 (+64 second pass)
    const int aq   = (tid & 3) * 4;
    const int bkr  = tid >> 5;          // 0..7  (+8 second pass)
    const int bcq  = (tid & 31) * 4;

    for (int k0 = 0; k0 < K; k0 += 16) {
        #pragma unroll
        for (int i = 0; i < 2; i++) {
            int row = arow + i * 64;
            float4 va = *(const float4*)(A + (size_t)(m0 + row) * K + k0 + aq);
            As[aq + 0][row] = va.x;
            As[aq + 1][row] = va.y;
            As[aq + 2][row] = va.z;
            As[aq + 3][row] = va.w;
        }
        #pragma unroll
        for (int i = 0; i < 2; i++) {
            int kr = bkr + i * 8;
            *(float4*)(&Bs[kr][bcq]) =
                *(const float4*)(B + (size_t)(k0 + kr) * N + n0 + bcq);
        }
        __syncthreads();
        #pragma unroll
        for (int k = 0; k < 16; k++) {
            float a[8], b[8];
            *(float4*)(a)     = *(const float4*)(&As[k][ty * 8]);
            *(float4*)(a + 4) = *(const float4*)(&As[k][ty * 8 + 4]);
            *(float4*)(b)     = *(const float4*)(&Bs[k][tx * 8]);
            *(float4*)(b + 4) = *(const float4*)(&Bs[k][tx * 8 + 4]);
            #pragma unroll
            for (int i = 0; i < 8; i++)
                #pragma unroll
                for (int j = 0; j < 8; j++)
                    acc[i][j] = fmaf(a[i], b[j], acc[i][j]);
        }
        __syncthreads();
    }

    #pragma unroll
    for (int i = 0; i < 8; i++) {
        const int m = m0 + ty * 8 + i;
        #pragma unroll
        for (int j = 0; j < 8; j++) {
            const int n = n0 + tx * 8 + j;
            float vv = acc[i][j] + bias[n];
            if (EPI == EPI_GELU)
                vv = 0.5f * vv * (1.0f + erff(vv * 0.70710678118654752f));
            if (EPI == EPI_RES)
                vv += R[(size_t)m * N + n];
            if (SCATTER) {  // scatter [tok, C] -> [b, h, t, d] (N==1024 here)
                const int bb = m >> 11, t = m & (SEQ - 1);
                const int hh = n >> 6,  d = n & 63;
                C[(((size_t)(bb * HEADS + hh)) * SEQ + t) * HD + d] = vv;
            } else {
                C[(size_t)m * N + n] = vv;
            }
        }
    }
}

// ---------------- fused attention, online softmax ------------------------------
// grid (32 q-tiles, 32 batch*heads), 256 threads.
// Each block: 64 query rows of one (b,h). Thread (r = tid>>2, c4 = tid&3):
// owns row r; key cols c = 4j+c4 (j<8) per tile; output dims d = 16*i4+4*c4+e.
#define KT 32

__global__ __launch_bounds__(256) void attn_kernel(
    const float* __restrict__ Q, const float* __restrict__ K,
    const float* __restrict__ V, float* __restrict__ O)
{
    __shared__ float Ks[KT][68];
    __shared__ float Vs[KT][68];
    __shared__ float Ps[64][KT + 4];
    const int qt  = blockIdx.x;      // 0..31
    const int bh  = blockIdx.y;      // 0..31  (= b*16 + h)
    const int tid = threadIdx.x;
    const int r   = tid >> 2;        // 0..63
    const int c4  = tid & 3;

    const size_t base = (size_t)bh * SEQ * HD;
    const int qrow = qt * 64 + r;

    // q row in registers, pre-scaled by 1/sqrt(64)
    float qreg[64];
    {
        const float* qp = Q + base + (size_t)qrow * HD;
        #pragma unroll
        for (int k4 = 0; k4 < 16; k4++) {
            float4 t = *(const float4*)(qp + k4 * 4);
            qreg[k4 * 4 + 0] = t.x * 0.125f;
            qreg[k4 * 4 + 1] = t.y * 0.125f;
            qreg[k4 * 4 + 2] = t.z * 0.125f;
            qreg[k4 * 4 + 3] = t.w * 0.125f;
        }
    }

    float m = -INFINITY, l = 0.f;
    float Oacc[16];
    #pragma unroll
    for (int i = 0; i < 16; i++) Oacc[i] = 0.f;

    for (int kt = 0; kt < SEQ / KT; kt++) {
        __syncthreads();   // previous iteration fully consumed Ks/Vs/Ps
        #pragma unroll
        for (int i = 0; i < 2; i++) {
            int idx = tid + i * 256;          // 0..511
            int row = idx >> 4;               // 0..31
            int cq  = (idx & 15) * 4;
            *(float4*)(&Ks[row][cq]) =
                *(const float4*)(K + base + (size_t)(kt * KT + row) * HD + cq);
            *(float4*)(&Vs[row][cq]) =
                *(const float4*)(V + base + (size_t)(kt * KT + row) * HD + cq);
        }
        __syncthreads();

        // ---- S tile: 8 dot products per thread (cols c = 4j + c4) ----
        float s[8];
        #pragma unroll
        for (int j = 0; j < 8; j++) {
            const int c = j * 4 + c4;
            const float* kp = &Ks[c][0];
            float acc = 0.f;
            #pragma unroll
            for (int k4 = 0; k4 < 16; k4++) {
                float4 kv = *(const float4*)(kp + k4 * 4);
                acc = fmaf(qreg[k4 * 4 + 0], kv.x, acc);
                acc = fmaf(qreg[k4 * 4 + 1], kv.y, acc);
                acc = fmaf(qreg[k4 * 4 + 2], kv.z, acc);
                acc = fmaf(qreg[k4 * 4 + 3], kv.w, acc);
            }
            s[j] = acc;
        }

        // ---- online softmax update (row = 4 consecutive lanes) ----
        float tmax = s[0];
        #pragma unroll
        for (int j = 1; j < 8; j++) tmax = fmaxf(tmax, s[j]);
        tmax = fmaxf(tmax, __shfl_xor_sync(0xffffffffu, tmax, 1));
        tmax = fmaxf(tmax, __shfl_xor_sync(0xffffffffu, tmax, 2));
        const float newm = fmaxf(m, tmax);
        const float corr = __expf(m - newm);   // first tile: exp(-inf) = 0
        float psum = 0.f;
        #pragma unroll
        for (int j = 0; j < 8; j++) {
            float p = __expf(s[j] - newm);
            Ps[r][j * 4 + c4] = p;
            psum += p;
        }
        psum += __shfl_xor_sync(0xffffffffu, psum, 1);
        psum += __shfl_xor_sync(0xffffffffu, psum, 2);
        l = l * corr + psum;
        #pragma unroll
        for (int i = 0; i < 16; i++) Oacc[i] *= corr;
        m = newm;
        __syncthreads();   // Ps visible to all lanes of the row

        // ---- O += P @ V (thread dims d = 16*i4 + 4*c4 + e) ----
        #pragma unroll 4
        for (int j = 0; j < KT; j++) {
            const float pv = Ps[r][j];
            #pragma unroll
            for (int i4 = 0; i4 < 4; i4++) {
                float4 vv = *(const float4*)(&Vs[j][i4 * 16 + c4 * 4]);
                Oacc[i4 * 4 + 0] = fmaf(pv, vv.x, Oacc[i4 * 4 + 0]);
                Oacc[i4 * 4 + 1] = fmaf(pv, vv.y, Oacc[i4 * 4 + 1]);
                Oacc[i4 * 4 + 2] = fmaf(pv, vv.z, Oacc[i4 * 4 + 2]);
                Oacc[i4 * 4 + 3] = fmaf(pv, vv.w, Oacc[i4 * 4 + 3]);
            }
        }
    }

    // ---- write O back in [b, t, h*64+d] layout for the O-projection GEMM ----
    const float inv = 1.0f / l;
    const int bb = bh >> 4, hh = bh & 15;
    float* op = O + ((size_t)(bb * SEQ + qrow)) * DIM + hh * HD;
    #pragma unroll
    for (int i4 = 0; i4 < 4; i4++) {
        float4 w;
        w.x = Oacc[i4 * 4 + 0] * inv;
        w.y = Oacc[i4 * 4 + 1] * inv;
        w.z = Oacc[i4 * 4 + 2] * inv;
        w.w = Oacc[i4 * 4 + 3] * inv;
        *(float4*)(op + i4 * 16 + c4 * 4) = w;
    }
}

// ---------------- launch --------------------------------------------------------
extern "C" void kernel_launch(void* const* d_in, const int* in_sizes, int n_in,
                              void* d_out, int out_size)
{
    const float* x   = (const float*)d_in[0];
    const float* g1  = (const float*)d_in[1];
    const float* b1  = (const float*)d_in[2];
    const float* Wq  = (const float*)d_in[3];
    const float* bq  = (const float*)d_in[4];
    const float* Wk  = (const float*)d_in[5];
    const float* bk  = (const float*)d_in[6];
    const float* Wv  = (const float*)d_in[7];
    const float* bv  = (const float*)d_in[8];
    const float* Wo  = (const float*)d_in[9];
    const float* bo  = (const float*)d_in[10];
    const float* g2  = (const float*)d_in[11];
    const float* b2  = (const float*)d_in[12];
    const float* W1  = (const float*)d_in[13];
    const float* bf1 = (const float*)d_in[14];
    const float* W2  = (const float*)d_in[15];
    const float* bf2 = (const float*)d_in[16];
    float* out = (float*)d_out;

    float *h, *q, *k, *v, *o, *x1, *h2, *a;
    cudaGetSymbolAddress((void**)&h,  g_h);
    cudaGetSymbolAddress((void**)&q,  g_q);
    cudaGetSymbolAddress((void**)&k,  g_k);
    cudaGetSymbolAddress((void**)&v,  g_v);
    cudaGetSymbolAddress((void**)&o,  g_o);
    cudaGetSymbolAddress((void**)&x1, g_x1);
    cudaGetSymbolAddress((void**)&h2, g_h2);
    cudaGetSymbolAddress((void**)&a,  g_a);

    // h = LN1(x)
    ln_kernel<<<TOK, 256>>>(x, g1, b1, h);
    // q,k,v = h@W + b, scattered to [b,h,t,d]
    gemm_kernel<EPI_NONE, true ><<<dim3(DIM/128, TOK/128), 256>>>(h, Wq, bq, nullptr, q, TOK, DIM, DIM);
    gemm_kernel<EPI_NONE, true ><<<dim3(DIM/128, TOK/128), 256>>>(h, Wk, bk, nullptr, k, TOK, DIM, DIM);
    gemm_kernel<EPI_NONE, true ><<<dim3(DIM/128, TOK/128), 256>>>(h, Wv, bv, nullptr, v, TOK, DIM, DIM);
    // o = softmax(qk^T/sqrt(d)) v, written as [b,t,C]
    attn_kernel<<<dim3(SEQ/64, BATCH*HEADS), 256>>>(q, k, v, o);
    // x1 = x + o@Wo + bo
    gemm_kernel<EPI_RES,  false><<<dim3(DIM/128, TOK/128), 256>>>(o, Wo, bo, x, x1, TOK, DIM, DIM);
    // h2 = LN2(x1)
    ln_kernel<<<TOK, 256>>>(x1, g2, b2, h2);
    // a = gelu(h2@W1 + bf1)
    gemm_kernel<EPI_GELU, false><<<dim3(HIDDEN/128, TOK/128), 256>>>(h2, W1, bf1, nullptr, a, TOK, HIDDEN, DIM);
    // out = x1 + a@W2 + bf2
    gemm_kernel<EPI_RES,  false><<<dim3(DIM/128, TOK/128), 256>>>(a, W2, bf2, x1, out, TOK, DIM, HIDDEN);
}